// round 6
// baseline (speedup 1.0000x reference)
#include <cuda_runtime.h>

#define BB 8
#define HH 128
#define WWD 128
#define DD4 128          // D / 4 (float4 lanes)

// Scratch (allocation-free rule: __device__ globals)
__device__ float4 g_partial[BB * HH * 5 * DD4];  // [b][h][k][d4], k=0..3 w-region sums, k=4 full row
__device__ float4 g_sums[BB * 17 * DD4];         // [b][r][d4], r=0..15 region sums, r=16 global

__device__ __forceinline__ float4 f4add(float4 a, float4 b) {
    return make_float4(a.x + b.x, a.y + b.y, a.z + b.z, a.w + b.w);
}
__device__ __forceinline__ float4 f4fma(float s, float4 a, float4 b) {
    return make_float4(fmaf(s, a.x, b.x), fmaf(s, a.y, b.y),
                       fmaf(s, a.z, b.z), fmaf(s, a.w, b.w));
}

// ---------------------------------------------------------------------------
// k1: per (b,h) row — per-w-region partial sums + full row sum.
// grid = B*H = 1024 blocks, 128 threads. Exact R2 form (measured 44.0us, 78%).
// ---------------------------------------------------------------------------
__global__ __launch_bounds__(128) void k1_rowsums(const float4* __restrict__ feat) {
    const int bh = blockIdx.x;                 // b*128 + h
    const int t  = threadIdx.x;                // d4 lane
    const float4* row = feat + (size_t)bh * WWD * DD4 + t;

    float4 a0 = make_float4(0.f, 0.f, 0.f, 0.f);
    float4 a1 = a0, a2 = a0, a3 = a0, af = a0;

    #pragma unroll 4
    for (int w = 0; w < WWD; ++w) {
        float4 v = __ldg(&row[(size_t)w * DD4]);
        af = f4add(af, v);
        // region j covers w in [24j, 24j+32)
        if (w < 32)             a0 = f4add(a0, v);
        if (w >= 24 && w < 56)  a1 = f4add(a1, v);
        if (w >= 48 && w < 80)  a2 = f4add(a2, v);
        if (w >= 72 && w < 104) a3 = f4add(a3, v);
    }

    float4* p = g_partial + (size_t)bh * 5 * DD4 + t;
    p[0 * DD4] = a0;
    p[1 * DD4] = a1;
    p[2 * DD4] = a2;
    p[3 * DD4] = a3;
    p[4 * DD4] = af;
}

// ---------------------------------------------------------------------------
// k1b: reduce partials over h into 16 region sums + global sum.
// grid = B*17 blocks, 128 threads. ~10 MiB, L2-hot, ~3 us.
// ---------------------------------------------------------------------------
__global__ __launch_bounds__(128) void k1b_reduce() {
    const int b = blockIdx.x / 17;
    const int r = blockIdx.x % 17;
    const int t = threadIdx.x;

    float4 acc = make_float4(0.f, 0.f, 0.f, 0.f);
    if (r < 16) {
        const int i  = r >> 2;     // h-region index
        const int j  = r & 3;      // w-region index
        const int h0 = 24 * i;     // h-region covers [24i, 24i+32)
        #pragma unroll 8
        for (int hh = 0; hh < 32; ++hh) {
            float4 v = g_partial[((size_t)(b * HH + h0 + hh) * 5 + j) * DD4 + t];
            acc = f4add(acc, v);
        }
    } else {
        #pragma unroll 8
        for (int h = 0; h < HH; ++h) {
            float4 v = g_partial[((size_t)(b * HH + h) * 5 + 4) * DD4 + t];
            acc = f4add(acc, v);
        }
    }
    g_sums[(size_t)(b * 17 + r) * DD4 + t] = acc;
}

// ---------------------------------------------------------------------------
// k2: elementwise pass. grid = B*H = 1024 blocks, 512 threads.
//   threadIdx = wq*128 + t (wq = w-quarter, t = d4 lane).
// Reads: __ldcs (last-use, evict-first — don't pollute L2).
// Writes: default STG (write-allocate; L2 buffers writebacks into bursts).
// Software pipeline: prefetch next 8-group while computing current.
// ---------------------------------------------------------------------------
__global__ __launch_bounds__(512) void k2_apply(const float4* __restrict__ feat,
                                                float4* __restrict__ out) {
    const int bh = blockIdx.x;
    const int b  = bh >> 7;
    const int h  = bh & 127;
    const int t  = threadIdx.x & 127;   // d4 lane
    const int wq = threadIdx.x >> 7;    // w quarter

    __shared__ float4 s_wc[WWD];        // {ww0..ww3} * coef, per w

    // per-h Gaussian weights (uniform across block)
    const float hc = h * (3.0f / 127.0f);
    float hwv[4];
    float HS = 0.f;
    #pragma unroll
    for (int i = 0; i < 4; ++i) {
        float d = hc - (float)i;
        hwv[i] = __expf(-0.125f * d * d);
        HS += hwv[i];
    }

    if (threadIdx.x < WWD) {
        const int w = threadIdx.x;
        const float wc = w * (3.0f / 127.0f);
        float e[4];
        float WS = 0.f;
        #pragma unroll
        for (int j = 0; j < 4; ++j) {
            float d = wc - (float)j;
            e[j] = __expf(-0.125f * d * d);
            WS += e[j];
        }
        const float c = 0.6f / (1024.0f * (HS * WS + 1e-8f));
        s_wc[w] = make_float4(e[0] * c, e[1] * c, e[2] * c, e[3] * c);
    }
    __syncthreads();

    // colagg[j] + global term for this d4 lane (g_sums tiny, L2-hot)
    const float4* srow = g_sums + (size_t)b * 17 * DD4 + t;
    float4 ca[4];
    #pragma unroll
    for (int j = 0; j < 4; ++j) ca[j] = make_float4(0.f, 0.f, 0.f, 0.f);
    #pragma unroll
    for (int i = 0; i < 4; ++i)
        #pragma unroll
        for (int j = 0; j < 4; ++j)
            ca[j] = f4fma(hwv[i], srow[(i * 4 + j) * DD4], ca[j]);

    float4 gs = srow[16 * DD4];
    const float gscale = 0.4f / 16384.0f;
    float4 base = make_float4(gs.x * gscale, gs.y * gscale, gs.z * gscale, gs.w * gscale);

    const float4* frow = feat + ((size_t)bh * WWD + wq * 32) * DD4 + t;
    float4*       orow = out  + ((size_t)bh * WWD + wq * 32) * DD4 + t;
    const int w0 = wq * 32;

    // Software-pipelined: 4 groups of 8 with one group in flight ahead.
    float4 v[8], vn[8];
    #pragma unroll
    for (int k = 0; k < 8; ++k)
        v[k] = __ldcs(&frow[(size_t)k * DD4]);

    #pragma unroll
    for (int g = 0; g < 4; ++g) {
        if (g < 3) {
            #pragma unroll
            for (int k = 0; k < 8; ++k)
                vn[k] = __ldcs(&frow[(size_t)((g + 1) * 8 + k) * DD4]);
        }
        #pragma unroll
        for (int k = 0; k < 8; ++k) {
            const float4 wc = s_wc[w0 + g * 8 + k];
            float4 r;
            r.x = v[k].x + base.x + wc.x * ca[0].x + wc.y * ca[1].x + wc.z * ca[2].x + wc.w * ca[3].x;
            r.y = v[k].y + base.y + wc.x * ca[0].y + wc.y * ca[1].y + wc.z * ca[2].y + wc.w * ca[3].y;
            r.z = v[k].z + base.z + wc.x * ca[0].z + wc.y * ca[1].z + wc.z * ca[2].z + wc.w * ca[3].z;
            r.w = v[k].w + base.w + wc.x * ca[0].w + wc.y * ca[1].w + wc.z * ca[2].w + wc.w * ca[3].w;
            orow[(size_t)(g * 8 + k) * DD4] = r;
        }
        #pragma unroll
        for (int k = 0; k < 8; ++k)
            v[k] = vn[k];
    }
}

// ---------------------------------------------------------------------------
extern "C" void kernel_launch(void* const* d_in, const int* in_sizes, int n_in,
                              void* d_out, int out_size) {
    const float4* feat = (const float4*)d_in[0];
    float4*       out  = (float4*)d_out;

    k1_rowsums<<<BB * HH, 128>>>(feat);
    k1b_reduce<<<BB * 17, 128>>>();
    k2_apply<<<BB * HH, 512>>>(feat, out);
}

// round 7
// speedup vs baseline: 1.0554x; 1.0554x over previous
#include <cuda_runtime.h>

#define BB 8
#define HH 128
#define WWD 128
#define DD4 128          // D / 4 (float4 lanes)

// Scratch (allocation-free rule: __device__ globals)
__device__ float4 g_partial[BB * HH * 5 * DD4];  // [b][h][k][d4], k=0..3 w-region sums, k=4 full row
__device__ float4 g_sums[BB * 17 * DD4];         // [b][r][d4], r=0..15 region sums, r=16 global

__device__ __forceinline__ float4 f4add(float4 a, float4 b) {
    return make_float4(a.x + b.x, a.y + b.y, a.z + b.z, a.w + b.w);
}
__device__ __forceinline__ float4 f4fma(float s, float4 a, float4 b) {
    return make_float4(fmaf(s, a.x, b.x), fmaf(s, a.y, b.y),
                       fmaf(s, a.z, b.z), fmaf(s, a.w, b.w));
}

// ---------------------------------------------------------------------------
// k1: per (b,h) row — per-w-region partial sums + full row sum.
// grid = B*H = 1024 blocks, 128 threads (proven ceiling geometry).
// Cache policy: w<80 evict-first (__ldcs), w>=80 normal (__ldg) to pin the
// w-tail (~96 MiB across all rows) in L2 for k2.
// ---------------------------------------------------------------------------
__global__ __launch_bounds__(128) void k1_rowsums(const float4* __restrict__ feat) {
    const int bh = blockIdx.x;                 // b*128 + h
    const int t  = threadIdx.x;                // d4 lane
    const float4* row = feat + (size_t)bh * WWD * DD4 + t;

    float4 a0 = make_float4(0.f, 0.f, 0.f, 0.f);
    float4 a1 = a0, a2 = a0, a3 = a0, af = a0;

    // region j covers w in [24j, 24j+32)
    #pragma unroll 4
    for (int w = 0; w < 80; ++w) {
        float4 v = __ldcs(&row[(size_t)w * DD4]);   // evict-first
        af = f4add(af, v);
        if (w < 32)             a0 = f4add(a0, v);
        if (w >= 24 && w < 56)  a1 = f4add(a1, v);
        if (w >= 48 && w < 80)  a2 = f4add(a2, v);
        if (w >= 72)            a3 = f4add(a3, v);
    }
    #pragma unroll 4
    for (int w = 80; w < WWD; ++w) {
        float4 v = __ldg(&row[(size_t)w * DD4]);    // allocate normal (pin)
        af = f4add(af, v);
        if (w < 104) a3 = f4add(a3, v);
    }

    float4* p = g_partial + (size_t)bh * 5 * DD4 + t;
    p[0 * DD4] = a0;
    p[1 * DD4] = a1;
    p[2 * DD4] = a2;
    p[3 * DD4] = a3;
    p[4 * DD4] = af;
}

// ---------------------------------------------------------------------------
// k1b: reduce partials over h into 16 region sums + global sum.
// grid = B*17 blocks, 128 threads. ~10 MiB, L2-hot, ~3 us.
// ---------------------------------------------------------------------------
__global__ __launch_bounds__(128) void k1b_reduce() {
    const int b = blockIdx.x / 17;
    const int r = blockIdx.x % 17;
    const int t = threadIdx.x;

    float4 acc = make_float4(0.f, 0.f, 0.f, 0.f);
    if (r < 16) {
        const int i  = r >> 2;     // h-region index
        const int j  = r & 3;      // w-region index
        const int h0 = 24 * i;     // h-region covers [24i, 24i+32)
        #pragma unroll 8
        for (int hh = 0; hh < 32; ++hh) {
            float4 v = __ldcs(&g_partial[((size_t)(b * HH + h0 + hh) * 5 + j) * DD4 + t]);
            acc = f4add(acc, v);
        }
    } else {
        #pragma unroll 8
        for (int h = 0; h < HH; ++h) {
            float4 v = __ldcs(&g_partial[((size_t)(b * HH + h) * 5 + 4) * DD4 + t]);
            acc = f4add(acc, v);
        }
    }
    g_sums[(size_t)(b * 17 + r) * DD4 + t] = acc;
}

// ---------------------------------------------------------------------------
// k2: elementwise pass. grid = B*H = 1024 blocks, 512 threads.
//   threadIdx = wq*128 + t (wq = w-quarter, t = d4 lane).
// All reads __ldcs (last use; on-hit still hits, on-miss doesn't evict the
// pinned tail). All stores __stcs (never re-read; protect pinned lines).
// ---------------------------------------------------------------------------
__global__ __launch_bounds__(512) void k2_apply(const float4* __restrict__ feat,
                                                float4* __restrict__ out) {
    const int bh = blockIdx.x;
    const int b  = bh >> 7;
    const int h  = bh & 127;
    const int t  = threadIdx.x & 127;   // d4 lane
    const int wq = threadIdx.x >> 7;    // w quarter

    __shared__ float4 s_wc[WWD];        // {ww0..ww3} * coef, per w

    // per-h Gaussian weights (uniform across block)
    const float hc = h * (3.0f / 127.0f);
    float hwv[4];
    float HS = 0.f;
    #pragma unroll
    for (int i = 0; i < 4; ++i) {
        float d = hc - (float)i;
        hwv[i] = __expf(-0.125f * d * d);
        HS += hwv[i];
    }

    if (threadIdx.x < WWD) {
        const int w = threadIdx.x;
        const float wc = w * (3.0f / 127.0f);
        float e[4];
        float WS = 0.f;
        #pragma unroll
        for (int j = 0; j < 4; ++j) {
            float d = wc - (float)j;
            e[j] = __expf(-0.125f * d * d);
            WS += e[j];
        }
        const float c = 0.6f / (1024.0f * (HS * WS + 1e-8f));
        s_wc[w] = make_float4(e[0] * c, e[1] * c, e[2] * c, e[3] * c);
    }
    __syncthreads();

    // colagg[j] + global term for this d4 lane (g_sums tiny, L2-hot)
    const float4* srow = g_sums + (size_t)b * 17 * DD4 + t;
    float4 ca[4];
    #pragma unroll
    for (int j = 0; j < 4; ++j) ca[j] = make_float4(0.f, 0.f, 0.f, 0.f);
    #pragma unroll
    for (int i = 0; i < 4; ++i)
        #pragma unroll
        for (int j = 0; j < 4; ++j)
            ca[j] = f4fma(hwv[i], srow[(i * 4 + j) * DD4], ca[j]);

    float4 gs = srow[16 * DD4];
    const float gscale = 0.4f / 16384.0f;
    float4 base = make_float4(gs.x * gscale, gs.y * gscale, gs.z * gscale, gs.w * gscale);

    const float4* frow = feat + ((size_t)bh * WWD + wq * 32) * DD4 + t;
    float4*       orow = out  + ((size_t)bh * WWD + wq * 32) * DD4 + t;
    const int w0 = wq * 32;

    // 4 groups of 8: front-batch 8 independent loads, then compute+store 8.
    #pragma unroll
    for (int g = 0; g < 4; ++g) {
        float4 v[8];
        #pragma unroll
        for (int k = 0; k < 8; ++k)
            v[k] = __ldcs(&frow[(size_t)(g * 8 + k) * DD4]);

        #pragma unroll
        for (int k = 0; k < 8; ++k) {
            const float4 wc = s_wc[w0 + g * 8 + k];
            float4 r;
            r.x = v[k].x + base.x + wc.x * ca[0].x + wc.y * ca[1].x + wc.z * ca[2].x + wc.w * ca[3].x;
            r.y = v[k].y + base.y + wc.x * ca[0].y + wc.y * ca[1].y + wc.z * ca[2].y + wc.w * ca[3].y;
            r.z = v[k].z + base.z + wc.x * ca[0].z + wc.y * ca[1].z + wc.z * ca[2].z + wc.w * ca[3].z;
            r.w = v[k].w + base.w + wc.x * ca[0].w + wc.y * ca[1].w + wc.z * ca[2].w + wc.w * ca[3].w;
            __stcs(&orow[(size_t)(g * 8 + k) * DD4], r);
        }
    }
}

// ---------------------------------------------------------------------------
extern "C" void kernel_launch(void* const* d_in, const int* in_sizes, int n_in,
                              void* d_out, int out_size) {
    const float4* feat = (const float4*)d_in[0];
    float4*       out  = (float4*)d_out;

    k1_rowsums<<<BB * HH, 128>>>(feat);
    k1b_reduce<<<BB * 17, 128>>>();
    k2_apply<<<BB * HH, 512>>>(feat, out);
}

// round 8
// speedup vs baseline: 1.0702x; 1.0140x over previous
#include <cuda_runtime.h>

#define BB 8
#define HH 128
#define WWD 128
#define DD4 128          // D / 4 (float4 lanes)

// Scratch (allocation-free rule: __device__ globals)
__device__ float4 g_partial[BB * HH * 5 * DD4];  // [b][h][k][d4], k=0..3 w-region sums, k=4 full row
__device__ float4 g_sums[BB * 17 * DD4];         // [b][r][d4], r=0..15 region sums, r=16 global

__device__ __forceinline__ float4 f4add(float4 a, float4 b) {
    return make_float4(a.x + b.x, a.y + b.y, a.z + b.z, a.w + b.w);
}
__device__ __forceinline__ float4 f4fma(float s, float4 a, float4 b) {
    return make_float4(fmaf(s, a.x, b.x), fmaf(s, a.y, b.y),
                       fmaf(s, a.z, b.z), fmaf(s, a.w, b.w));
}

// ---------------------------------------------------------------------------
// k1: per (b,h) row — per-w-region partial sums + full row sum.
// grid = B*H = 1024 blocks, 128 threads. EXACT R2 form (fastest: 44.0us).
// Plain __ldg: LRU naturally leaves the w-tail of all rows in L2 for k2.
// ---------------------------------------------------------------------------
__global__ __launch_bounds__(128) void k1_rowsums(const float4* __restrict__ feat) {
    const int bh = blockIdx.x;                 // b*128 + h
    const int t  = threadIdx.x;                // d4 lane
    const float4* row = feat + (size_t)bh * WWD * DD4 + t;

    float4 a0 = make_float4(0.f, 0.f, 0.f, 0.f);
    float4 a1 = a0, a2 = a0, a3 = a0, af = a0;

    #pragma unroll 4
    for (int w = 0; w < WWD; ++w) {
        float4 v = __ldg(&row[(size_t)w * DD4]);
        af = f4add(af, v);
        // region j covers w in [24j, 24j+32)
        if (w < 32)             a0 = f4add(a0, v);
        if (w >= 24 && w < 56)  a1 = f4add(a1, v);
        if (w >= 48 && w < 80)  a2 = f4add(a2, v);
        if (w >= 72 && w < 104) a3 = f4add(a3, v);
    }

    float4* p = g_partial + (size_t)bh * 5 * DD4 + t;
    p[0 * DD4] = a0;
    p[1 * DD4] = a1;
    p[2 * DD4] = a2;
    p[3 * DD4] = a3;
    p[4 * DD4] = af;
}

// ---------------------------------------------------------------------------
// k1b: reduce partials over h into 16 region sums + global sum.
// grid = B*17 blocks, 128 threads. __ldcs reads: g_partial is dead after this
// and must not evict the resident feature tail.
// ---------------------------------------------------------------------------
__global__ __launch_bounds__(128) void k1b_reduce() {
    const int b = blockIdx.x / 17;
    const int r = blockIdx.x % 17;
    const int t = threadIdx.x;

    float4 acc = make_float4(0.f, 0.f, 0.f, 0.f);
    if (r < 16) {
        const int i  = r >> 2;     // h-region index
        const int j  = r & 3;      // w-region index
        const int h0 = 24 * i;     // h-region covers [24i, 24i+32)
        #pragma unroll 8
        for (int hh = 0; hh < 32; ++hh) {
            float4 v = __ldcs(&g_partial[((size_t)(b * HH + h0 + hh) * 5 + j) * DD4 + t]);
            acc = f4add(acc, v);
        }
    } else {
        #pragma unroll 8
        for (int h = 0; h < HH; ++h) {
            float4 v = __ldcs(&g_partial[((size_t)(b * HH + h) * 5 + 4) * DD4 + t]);
            acc = f4add(acc, v);
        }
    }
    g_sums[(size_t)(b * 17 + r) * DD4 + t] = acc;
}

// ---------------------------------------------------------------------------
// k2: elementwise pass, REVERSE w order (127 -> 0): consume the L2-resident
// w-tail left by k1's LRU before k2's own streaming can evict it.
// grid = B*H = 1024 blocks, 512 threads: threadIdx = wq*128 + t.
// Reads __ldcs (last use, don't evict unread tail on miss).
// Stores __stcs (never re-read, don't write-allocate over the tail).
// ---------------------------------------------------------------------------
__global__ __launch_bounds__(512) void k2_apply(const float4* __restrict__ feat,
                                                float4* __restrict__ out) {
    const int bh = blockIdx.x;
    const int b  = bh >> 7;
    const int h  = bh & 127;
    const int t  = threadIdx.x & 127;   // d4 lane
    const int wq = threadIdx.x >> 7;    // w quarter (reversed below)

    __shared__ float4 s_wc[WWD];        // {ww0..ww3} * coef, per w

    // per-h Gaussian weights (uniform across block)
    const float hc = h * (3.0f / 127.0f);
    float hwv[4];
    float HS = 0.f;
    #pragma unroll
    for (int i = 0; i < 4; ++i) {
        float d = hc - (float)i;
        hwv[i] = __expf(-0.125f * d * d);
        HS += hwv[i];
    }

    if (threadIdx.x < WWD) {
        const int w = threadIdx.x;
        const float wc = w * (3.0f / 127.0f);
        float e[4];
        float WS = 0.f;
        #pragma unroll
        for (int j = 0; j < 4; ++j) {
            float d = wc - (float)j;
            e[j] = __expf(-0.125f * d * d);
            WS += e[j];
        }
        const float c = 0.6f / (1024.0f * (HS * WS + 1e-8f));
        s_wc[w] = make_float4(e[0] * c, e[1] * c, e[2] * c, e[3] * c);
    }
    __syncthreads();

    // colagg[j] + global term for this d4 lane (g_sums tiny, L2-hot)
    const float4* srow = g_sums + (size_t)b * 17 * DD4 + t;
    float4 ca[4];
    #pragma unroll
    for (int j = 0; j < 4; ++j) ca[j] = make_float4(0.f, 0.f, 0.f, 0.f);
    #pragma unroll
    for (int i = 0; i < 4; ++i)
        #pragma unroll
        for (int j = 0; j < 4; ++j)
            ca[j] = f4fma(hwv[i], srow[(i * 4 + j) * DD4], ca[j]);

    float4 gs = srow[16 * DD4];
    const float gscale = 0.4f / 16384.0f;
    float4 base = make_float4(gs.x * gscale, gs.y * gscale, gs.z * gscale, gs.w * gscale);

    // Reverse quarter assignment: wq=0 handles the highest w block first.
    const int rq = 3 - wq;              // reversed quarter index
    const int w0 = rq * 32;
    const float4* frow = feat + ((size_t)bh * WWD + w0) * DD4 + t;
    float4*       orow = out  + ((size_t)bh * WWD + w0) * DD4 + t;

    // Groups processed high-w first within the quarter as well.
    #pragma unroll
    for (int g = 3; g >= 0; --g) {
        float4 v[8];
        #pragma unroll
        for (int k = 0; k < 8; ++k)
            v[k] = __ldcs(&frow[(size_t)(g * 8 + k) * DD4]);

        #pragma unroll
        for (int k = 0; k < 8; ++k) {
            const float4 wc = s_wc[w0 + g * 8 + k];
            float4 r;
            r.x = v[k].x + base.x + wc.x * ca[0].x + wc.y * ca[1].x + wc.z * ca[2].x + wc.w * ca[3].x;
            r.y = v[k].y + base.y + wc.x * ca[0].y + wc.y * ca[1].y + wc.z * ca[2].y + wc.w * ca[3].y;
            r.z = v[k].z + base.z + wc.x * ca[0].z + wc.y * ca[1].z + wc.z * ca[2].z + wc.w * ca[3].z;
            r.w = v[k].w + base.w + wc.x * ca[0].w + wc.y * ca[1].w + wc.z * ca[2].w + wc.w * ca[3].w;
            __stcs(&orow[(size_t)(g * 8 + k) * DD4], r);
        }
    }
}

// ---------------------------------------------------------------------------
extern "C" void kernel_launch(void* const* d_in, const int* in_sizes, int n_in,
                              void* d_out, int out_size) {
    const float4* feat = (const float4*)d_in[0];
    float4*       out  = (float4*)d_out;

    k1_rowsums<<<BB * HH, 128>>>(feat);
    k1b_reduce<<<BB * 17, 128>>>();
    k2_apply<<<BB * HH, 512>>>(feat, out);
}